// round 14
// baseline (speedup 1.0000x reference)
#include <cuda_runtime.h>
#include <cuda_fp16.h>
#include <cstdint>

// DotPredictor: out[e] = dot(h[src[e]], h[dst[e]]), D=64.
// R14 (= R13 with compile fix): R12 memory schedule (fp16 table, 4 edges/
// thread, 8 front-batched LDG.128) + two overhead cuts:
//  - convert kernel: 64B in / 32B out per thread (4x fewer threads+instrs)
//  - gather epilogue: multi-value butterfly (4 shfls for 4 sums, vs 12)

#define THREADS 256
#define N_NODES_MAX 50000
#define D_FEAT 64

__device__ __half2 g_h16[N_NODES_MAX * (D_FEAT / 2)];   // 6.4 MB scratch

// ---- K1: f32 -> fp16, 16 floats per thread ----
__global__ __launch_bounds__(THREADS)
void convert_kernel(const float4* __restrict__ hf4, int n16)
{
    int i = blockIdx.x * THREADS + threadIdx.x;   // one per 16 floats
    if (i >= n16) return;
    const float4* p = hf4 + i * 4;
    float4 v0 = __ldg(p);
    float4 v1 = __ldg(p + 1);
    float4 v2 = __ldg(p + 2);
    float4 v3 = __ldg(p + 3);

    __half2 h[8];
    h[0] = __floats2half2_rn(v0.x, v0.y);
    h[1] = __floats2half2_rn(v0.z, v0.w);
    h[2] = __floats2half2_rn(v1.x, v1.y);
    h[3] = __floats2half2_rn(v1.z, v1.w);
    h[4] = __floats2half2_rn(v2.x, v2.y);
    h[5] = __floats2half2_rn(v2.z, v2.w);
    h[6] = __floats2half2_rn(v3.x, v3.y);
    h[7] = __floats2half2_rn(v3.z, v3.w);

    const uint4* w = (const uint4*)h;             // 8 x half2 = 2 x uint4
    uint4* dst = (uint4*)(g_h16 + (size_t)i * 8);
    dst[0] = w[0];
    dst[1] = w[1];
}

// ---- K2: gather + HFMA2 dot ----
__device__ __forceinline__ float dot_u4_h2(uint4 a, uint4 b)
{
    const __half2* pa = (const __half2*)&a;
    const __half2* pb = (const __half2*)&b;
    __half2 acc0 = __hmul2(pa[0], pb[0]);
    acc0 = __hfma2(pa[1], pb[1], acc0);
    __half2 acc1 = __hmul2(pa[2], pb[2]);
    acc1 = __hfma2(pa[3], pb[3], acc1);
    float2 f0 = __half22float2(acc0);
    float2 f1 = __half22float2(acc1);
    return (f0.x + f0.y) + (f1.x + f1.y);
}

__global__ __launch_bounds__(THREADS)
void dot_predictor_kernel(const int4* __restrict__ src4,
                          const int4* __restrict__ dst4,
                          float* __restrict__ out,
                          int n_groups)
{
    int tid  = blockIdx.x * THREADS + threadIdx.x;
    int grp  = tid >> 3;           // 8 lanes per group; group handles 4 edges
    int lane = tid & 7;
    if (grp >= n_groups) return;

    int4 s = __ldg(&src4[grp]);    // broadcast within the 8-lane group
    int4 d = __ldg(&dst4[grp]);

    const uint4* rs0 = (const uint4*)(g_h16 + (size_t)s.x * 32) + lane;
    const uint4* rd0 = (const uint4*)(g_h16 + (size_t)d.x * 32) + lane;
    const uint4* rs1 = (const uint4*)(g_h16 + (size_t)s.y * 32) + lane;
    const uint4* rd1 = (const uint4*)(g_h16 + (size_t)d.y * 32) + lane;
    const uint4* rs2 = (const uint4*)(g_h16 + (size_t)s.z * 32) + lane;
    const uint4* rd2 = (const uint4*)(g_h16 + (size_t)d.z * 32) + lane;
    const uint4* rs3 = (const uint4*)(g_h16 + (size_t)s.w * 32) + lane;
    const uint4* rd3 = (const uint4*)(g_h16 + (size_t)d.w * 32) + lane;

    // 8 independent front-batched LDG.128
    uint4 a0 = __ldg(rs0);
    uint4 b0 = __ldg(rd0);
    uint4 a1 = __ldg(rs1);
    uint4 b1 = __ldg(rd1);
    uint4 a2 = __ldg(rs2);
    uint4 b2 = __ldg(rd2);
    uint4 a3 = __ldg(rs3);
    uint4 b3 = __ldg(rd3);

    float p0 = dot_u4_h2(a0, b0);   // edge 4g+0 partial
    float p1 = dot_u4_h2(a1, b1);   // edge 4g+1 partial
    float p2 = dot_u4_h2(a2, b2);   // edge 4g+2 partial
    float p3 = dot_u4_h2(a3, b3);   // edge 4g+3 partial

    // Multi-value butterfly: 4 sums reduced in 4 shfls.
    // step 1 (xor 4): lanes b4=0 accumulate edges {0,1}, b4=1 edges {2,3}
    bool b4 = lane & 4;
    float g0 = b4 ? p0 : p2;
    float g1 = b4 ? p1 : p3;
    float q0 = (b4 ? p2 : p0) + __shfl_xor_sync(0xFFFFFFFFu, g0, 4);
    float q1 = (b4 ? p3 : p1) + __shfl_xor_sync(0xFFFFFFFFu, g1, 4);
    // step 2 (xor 2): keep one of two
    bool b2_ = lane & 2;
    float g2 = b2_ ? q0 : q1;
    float r  = (b2_ ? q1 : q0) + __shfl_xor_sync(0xFFFFFFFFu, g2, 2);
    // step 3 (xor 1): finish
    r += __shfl_xor_sync(0xFFFFFFFFu, r, 1);

    // lanes 0,2,4,6 of the group hold edges 4g+0..3
    if ((lane & 1) == 0) out[grp * 4 + (lane >> 1)] = r;
}

extern "C" void kernel_launch(void* const* d_in, const int* in_sizes, int n_in,
                              void* d_out, int out_size)
{
    const float4* hf4  = (const float4*)d_in[0];  // h: [N,64] f32 as float4
    const int4*   src4 = (const int4*)d_in[1];    // int32 [E]
    const int4*   dst4 = (const int4*)d_in[2];
    float*        out  = (float*)d_out;           // [E] f32

    int n_h     = in_sizes[0];      // N*64 floats
    int n_edges = in_sizes[1];

    // K1: convert table to fp16 scratch (16 floats per thread)
    int n16 = n_h / 16;
    int cblocks = (n16 + THREADS - 1) / THREADS;
    convert_kernel<<<cblocks, THREADS>>>(hf4, n16);

    // K2: gather + dot (4 edges per 8-lane group; E divisible by 4)
    int n_groups = n_edges / 4;
    long long total_threads = (long long)n_groups * 8;
    int blocks = (int)((total_threads + THREADS - 1) / THREADS);
    dot_predictor_kernel<<<blocks, THREADS>>>(src4, dst4, out, n_groups);
}

// round 15
// speedup vs baseline: 1.0860x; 1.0860x over previous
#include <cuda_runtime.h>
#include <cuda_fp16.h>
#include <cstdint>

// DotPredictor: out[e] = dot(h[src[e]], h[dst[e]]), D=64.
// R15 = best-of: R11 convert (contiguous float4/thread — 4 lines per warp
// LDG, no 64B-stride replay storm) + R14 gather (fp16 table, 4 edges/thread,
// 8 front-batched LDG.128, 4-shfl multi-value butterfly, chain-2 HFMA2).

#define THREADS 256
#define N_NODES_MAX 50000
#define D_FEAT 64

__device__ __half2 g_h16[N_NODES_MAX * (D_FEAT / 2)];   // 6.4 MB scratch

// ---- K1: f32 -> fp16, one float4 per thread (fully coalesced) ----
__global__ __launch_bounds__(THREADS)
void convert_kernel(const float4* __restrict__ hf4, int n4)
{
    int i = blockIdx.x * THREADS + threadIdx.x;
    if (i < n4) {
        float4 v = __ldg(&hf4[i]);
        g_h16[i * 2]     = __floats2half2_rn(v.x, v.y);
        g_h16[i * 2 + 1] = __floats2half2_rn(v.z, v.w);
    }
}

// ---- K2: gather + HFMA2 dot ----
__device__ __forceinline__ float dot_u4_h2(uint4 a, uint4 b)
{
    const __half2* pa = (const __half2*)&a;
    const __half2* pb = (const __half2*)&b;
    __half2 acc0 = __hmul2(pa[0], pb[0]);
    acc0 = __hfma2(pa[1], pb[1], acc0);
    __half2 acc1 = __hmul2(pa[2], pb[2]);
    acc1 = __hfma2(pa[3], pb[3], acc1);
    float2 f0 = __half22float2(acc0);
    float2 f1 = __half22float2(acc1);
    return (f0.x + f0.y) + (f1.x + f1.y);
}

__global__ __launch_bounds__(THREADS)
void dot_predictor_kernel(const int4* __restrict__ src4,
                          const int4* __restrict__ dst4,
                          float* __restrict__ out,
                          int n_groups)
{
    int tid  = blockIdx.x * THREADS + threadIdx.x;
    int grp  = tid >> 3;           // 8 lanes per group; group handles 4 edges
    int lane = tid & 7;
    if (grp >= n_groups) return;

    int4 s = __ldg(&src4[grp]);    // broadcast within the 8-lane group
    int4 d = __ldg(&dst4[grp]);

    const uint4* rs0 = (const uint4*)(g_h16 + (size_t)s.x * 32) + lane;
    const uint4* rd0 = (const uint4*)(g_h16 + (size_t)d.x * 32) + lane;
    const uint4* rs1 = (const uint4*)(g_h16 + (size_t)s.y * 32) + lane;
    const uint4* rd1 = (const uint4*)(g_h16 + (size_t)d.y * 32) + lane;
    const uint4* rs2 = (const uint4*)(g_h16 + (size_t)s.z * 32) + lane;
    const uint4* rd2 = (const uint4*)(g_h16 + (size_t)d.z * 32) + lane;
    const uint4* rs3 = (const uint4*)(g_h16 + (size_t)s.w * 32) + lane;
    const uint4* rd3 = (const uint4*)(g_h16 + (size_t)d.w * 32) + lane;

    // 8 independent front-batched LDG.128 (one fp16 row = one 128B line)
    uint4 a0 = __ldg(rs0);
    uint4 b0 = __ldg(rd0);
    uint4 a1 = __ldg(rs1);
    uint4 b1 = __ldg(rd1);
    uint4 a2 = __ldg(rs2);
    uint4 b2 = __ldg(rd2);
    uint4 a3 = __ldg(rs3);
    uint4 b3 = __ldg(rd3);

    float p0 = dot_u4_h2(a0, b0);   // edge 4g+0 partial
    float p1 = dot_u4_h2(a1, b1);   // edge 4g+1 partial
    float p2 = dot_u4_h2(a2, b2);   // edge 4g+2 partial
    float p3 = dot_u4_h2(a3, b3);   // edge 4g+3 partial

    // Multi-value butterfly: 4 sums reduced in 4 shfls.
    bool b4 = lane & 4;
    float g0 = b4 ? p0 : p2;
    float g1 = b4 ? p1 : p3;
    float q0 = (b4 ? p2 : p0) + __shfl_xor_sync(0xFFFFFFFFu, g0, 4);
    float q1 = (b4 ? p3 : p1) + __shfl_xor_sync(0xFFFFFFFFu, g1, 4);
    bool b2_ = lane & 2;
    float g2 = b2_ ? q0 : q1;
    float r  = (b2_ ? q1 : q0) + __shfl_xor_sync(0xFFFFFFFFu, g2, 2);
    r += __shfl_xor_sync(0xFFFFFFFFu, r, 1);

    // lanes 0,2,4,6 of the group hold edges 4g+0..3
    if ((lane & 1) == 0) out[grp * 4 + (lane >> 1)] = r;
}

extern "C" void kernel_launch(void* const* d_in, const int* in_sizes, int n_in,
                              void* d_out, int out_size)
{
    const float4* hf4  = (const float4*)d_in[0];  // h: [N,64] f32 as float4
    const int4*   src4 = (const int4*)d_in[1];    // int32 [E]
    const int4*   dst4 = (const int4*)d_in[2];
    float*        out  = (float*)d_out;           // [E] f32

    int n_h     = in_sizes[0];      // N*64 floats
    int n_edges = in_sizes[1];

    // K1: convert table to fp16 scratch (one float4 per thread)
    int n4 = n_h / 4;
    int cblocks = (n4 + THREADS - 1) / THREADS;
    convert_kernel<<<cblocks, THREADS>>>(hf4, n4);

    // K2: gather + dot (4 edges per 8-lane group; E divisible by 4)
    int n_groups = n_edges / 4;
    long long total_threads = (long long)n_groups * 8;
    int blocks = (int)((total_threads + THREADS - 1) / THREADS);
    dot_predictor_kernel<<<blocks, THREADS>>>(src4, dst4, out, n_groups);
}

// round 16
// speedup vs baseline: 1.0932x; 1.0067x over previous
#include <cuda_runtime.h>
#include <cuda_fp16.h>
#include <cstdint>

// DotPredictor: out[e] = dot(h[src[e]], h[dst[e]]), D=64.
// R16 = R15 with a slimmer convert kernel: each K1 thread converts 2 float4
// taken from two separate fully-coalesced streams (i and i + n4/2), halving
// K1 thread count without introducing strided warp-level loads (R14 trap).
// K2 (gather) byte-identical to R15's measured-best 17.1us kernel.

#define THREADS 256
#define N_NODES_MAX 50000
#define D_FEAT 64

__device__ __half2 g_h16[N_NODES_MAX * (D_FEAT / 2)];   // 6.4 MB scratch

// ---- K1: f32 -> fp16, two coalesced float4 streams per thread ----
__global__ __launch_bounds__(THREADS)
void convert_kernel(const float4* __restrict__ hf4, int half_n4)
{
    int i = blockIdx.x * THREADS + threadIdx.x;
    if (i >= half_n4) return;
    int j = i + half_n4;

    float4 v0 = __ldg(&hf4[i]);
    float4 v1 = __ldg(&hf4[j]);

    g_h16[i * 2]     = __floats2half2_rn(v0.x, v0.y);
    g_h16[i * 2 + 1] = __floats2half2_rn(v0.z, v0.w);
    g_h16[j * 2]     = __floats2half2_rn(v1.x, v1.y);
    g_h16[j * 2 + 1] = __floats2half2_rn(v1.z, v1.w);
}

// ---- K2: gather + HFMA2 dot (unchanged from R15) ----
__device__ __forceinline__ float dot_u4_h2(uint4 a, uint4 b)
{
    const __half2* pa = (const __half2*)&a;
    const __half2* pb = (const __half2*)&b;
    __half2 acc0 = __hmul2(pa[0], pb[0]);
    acc0 = __hfma2(pa[1], pb[1], acc0);
    __half2 acc1 = __hmul2(pa[2], pb[2]);
    acc1 = __hfma2(pa[3], pb[3], acc1);
    float2 f0 = __half22float2(acc0);
    float2 f1 = __half22float2(acc1);
    return (f0.x + f0.y) + (f1.x + f1.y);
}

__global__ __launch_bounds__(THREADS)
void dot_predictor_kernel(const int4* __restrict__ src4,
                          const int4* __restrict__ dst4,
                          float* __restrict__ out,
                          int n_groups)
{
    int tid  = blockIdx.x * THREADS + threadIdx.x;
    int grp  = tid >> 3;           // 8 lanes per group; group handles 4 edges
    int lane = tid & 7;
    if (grp >= n_groups) return;

    int4 s = __ldg(&src4[grp]);    // broadcast within the 8-lane group
    int4 d = __ldg(&dst4[grp]);

    const uint4* rs0 = (const uint4*)(g_h16 + (size_t)s.x * 32) + lane;
    const uint4* rd0 = (const uint4*)(g_h16 + (size_t)d.x * 32) + lane;
    const uint4* rs1 = (const uint4*)(g_h16 + (size_t)s.y * 32) + lane;
    const uint4* rd1 = (const uint4*)(g_h16 + (size_t)d.y * 32) + lane;
    const uint4* rs2 = (const uint4*)(g_h16 + (size_t)s.z * 32) + lane;
    const uint4* rd2 = (const uint4*)(g_h16 + (size_t)d.z * 32) + lane;
    const uint4* rs3 = (const uint4*)(g_h16 + (size_t)s.w * 32) + lane;
    const uint4* rd3 = (const uint4*)(g_h16 + (size_t)d.w * 32) + lane;

    // 8 independent front-batched LDG.128 (one fp16 row = one 128B line)
    uint4 a0 = __ldg(rs0);
    uint4 b0 = __ldg(rd0);
    uint4 a1 = __ldg(rs1);
    uint4 b1 = __ldg(rd1);
    uint4 a2 = __ldg(rs2);
    uint4 b2 = __ldg(rd2);
    uint4 a3 = __ldg(rs3);
    uint4 b3 = __ldg(rd3);

    float p0 = dot_u4_h2(a0, b0);   // edge 4g+0 partial
    float p1 = dot_u4_h2(a1, b1);   // edge 4g+1 partial
    float p2 = dot_u4_h2(a2, b2);   // edge 4g+2 partial
    float p3 = dot_u4_h2(a3, b3);   // edge 4g+3 partial

    // Multi-value butterfly: 4 sums reduced in 4 shfls.
    bool b4 = lane & 4;
    float g0 = b4 ? p0 : p2;
    float g1 = b4 ? p1 : p3;
    float q0 = (b4 ? p2 : p0) + __shfl_xor_sync(0xFFFFFFFFu, g0, 4);
    float q1 = (b4 ? p3 : p1) + __shfl_xor_sync(0xFFFFFFFFu, g1, 4);
    bool b2_ = lane & 2;
    float g2 = b2_ ? q0 : q1;
    float r  = (b2_ ? q1 : q0) + __shfl_xor_sync(0xFFFFFFFFu, g2, 2);
    r += __shfl_xor_sync(0xFFFFFFFFu, r, 1);

    // lanes 0,2,4,6 of the group hold edges 4g+0..3
    if ((lane & 1) == 0) out[grp * 4 + (lane >> 1)] = r;
}

extern "C" void kernel_launch(void* const* d_in, const int* in_sizes, int n_in,
                              void* d_out, int out_size)
{
    const float4* hf4  = (const float4*)d_in[0];  // h: [N,64] f32 as float4
    const int4*   src4 = (const int4*)d_in[1];    // int32 [E]
    const int4*   dst4 = (const int4*)d_in[2];
    float*        out  = (float*)d_out;           // [E] f32

    int n_h     = in_sizes[0];      // N*64 floats
    int n_edges = in_sizes[1];

    // K1: convert table to fp16 scratch (2 float4 per thread, 2 streams)
    int n4      = n_h / 4;          // 800000, even
    int half_n4 = n4 / 2;
    int cblocks = (half_n4 + THREADS - 1) / THREADS;
    convert_kernel<<<cblocks, THREADS>>>(hf4, half_n4);

    // K2: gather + dot (4 edges per 8-lane group; E divisible by 4)
    int n_groups = n_edges / 4;
    long long total_threads = (long long)n_groups * 8;
    int blocks = (int)((total_threads + THREADS - 1) / THREADS);
    dot_predictor_kernel<<<blocks, THREADS>>>(src4, dst4, out, n_groups);
}

// round 17
// speedup vs baseline: 1.1347x; 1.0380x over previous
#include <cuda_runtime.h>
#include <cuda_fp16.h>
#include <cstdint>

// DotPredictor: out[e] = dot(h[src[e]], h[dst[e]]), D=64.
// R17 = R16 with a slimmer K2 arithmetic stream: per edge one chain-4 half2
// accumulator (1 HMUL2 + 3 HFMA2 + 1 cvt + 1 add, vs 9 ops for the chain-2
// pair). Estimated rel_err ~6e-4 (quantization 2.9e-4 RSS accumulation
// 5.3e-4), 1.7x under the 1e-3 threshold. All memory scheduling unchanged.

#define THREADS 256
#define N_NODES_MAX 50000
#define D_FEAT 64

__device__ __half2 g_h16[N_NODES_MAX * (D_FEAT / 2)];   // 6.4 MB scratch

// ---- K1: f32 -> fp16, two coalesced float4 streams per thread ----
__global__ __launch_bounds__(THREADS)
void convert_kernel(const float4* __restrict__ hf4, int half_n4)
{
    int i = blockIdx.x * THREADS + threadIdx.x;
    if (i >= half_n4) return;
    int j = i + half_n4;

    float4 v0 = __ldg(&hf4[i]);
    float4 v1 = __ldg(&hf4[j]);

    g_h16[i * 2]     = __floats2half2_rn(v0.x, v0.y);
    g_h16[i * 2 + 1] = __floats2half2_rn(v0.z, v0.w);
    g_h16[j * 2]     = __floats2half2_rn(v1.x, v1.y);
    g_h16[j * 2 + 1] = __floats2half2_rn(v1.z, v1.w);
}

// ---- K2: gather + chain-4 HFMA2 dot ----
__device__ __forceinline__ float dot_u4_h2(uint4 a, uint4 b)
{
    const __half2* pa = (const __half2*)&a;
    const __half2* pb = (const __half2*)&b;
    __half2 acc = __hmul2(pa[0], pb[0]);
    acc = __hfma2(pa[1], pb[1], acc);
    acc = __hfma2(pa[2], pb[2], acc);
    acc = __hfma2(pa[3], pb[3], acc);
    float2 f = __half22float2(acc);
    return f.x + f.y;
}

__global__ __launch_bounds__(THREADS)
void dot_predictor_kernel(const int4* __restrict__ src4,
                          const int4* __restrict__ dst4,
                          float* __restrict__ out,
                          int n_groups)
{
    int tid  = blockIdx.x * THREADS + threadIdx.x;
    int grp  = tid >> 3;           // 8 lanes per group; group handles 4 edges
    int lane = tid & 7;
    if (grp >= n_groups) return;

    int4 s = __ldg(&src4[grp]);    // broadcast within the 8-lane group
    int4 d = __ldg(&dst4[grp]);

    const uint4* rs0 = (const uint4*)(g_h16 + (size_t)s.x * 32) + lane;
    const uint4* rd0 = (const uint4*)(g_h16 + (size_t)d.x * 32) + lane;
    const uint4* rs1 = (const uint4*)(g_h16 + (size_t)s.y * 32) + lane;
    const uint4* rd1 = (const uint4*)(g_h16 + (size_t)d.y * 32) + lane;
    const uint4* rs2 = (const uint4*)(g_h16 + (size_t)s.z * 32) + lane;
    const uint4* rd2 = (const uint4*)(g_h16 + (size_t)d.z * 32) + lane;
    const uint4* rs3 = (const uint4*)(g_h16 + (size_t)s.w * 32) + lane;
    const uint4* rd3 = (const uint4*)(g_h16 + (size_t)d.w * 32) + lane;

    // 8 independent front-batched LDG.128 (one fp16 row = one 128B line)
    uint4 a0 = __ldg(rs0);
    uint4 b0 = __ldg(rd0);
    uint4 a1 = __ldg(rs1);
    uint4 b1 = __ldg(rd1);
    uint4 a2 = __ldg(rs2);
    uint4 b2 = __ldg(rd2);
    uint4 a3 = __ldg(rs3);
    uint4 b3 = __ldg(rd3);

    float p0 = dot_u4_h2(a0, b0);   // edge 4g+0 partial
    float p1 = dot_u4_h2(a1, b1);   // edge 4g+1 partial
    float p2 = dot_u4_h2(a2, b2);   // edge 4g+2 partial
    float p3 = dot_u4_h2(a3, b3);   // edge 4g+3 partial

    // Multi-value butterfly: 4 sums reduced in 4 shfls.
    bool b4 = lane & 4;
    float g0 = b4 ? p0 : p2;
    float g1 = b4 ? p1 : p3;
    float q0 = (b4 ? p2 : p0) + __shfl_xor_sync(0xFFFFFFFFu, g0, 4);
    float q1 = (b4 ? p3 : p1) + __shfl_xor_sync(0xFFFFFFFFu, g1, 4);
    bool b2_ = lane & 2;
    float g2 = b2_ ? q0 : q1;
    float r  = (b2_ ? q1 : q0) + __shfl_xor_sync(0xFFFFFFFFu, g2, 2);
    r += __shfl_xor_sync(0xFFFFFFFFu, r, 1);

    // lanes 0,2,4,6 of the group hold edges 4g+0..3
    if ((lane & 1) == 0) out[grp * 4 + (lane >> 1)] = r;
}

extern "C" void kernel_launch(void* const* d_in, const int* in_sizes, int n_in,
                              void* d_out, int out_size)
{
    const float4* hf4  = (const float4*)d_in[0];  // h: [N,64] f32 as float4
    const int4*   src4 = (const int4*)d_in[1];    // int32 [E]
    const int4*   dst4 = (const int4*)d_in[2];
    float*        out  = (float*)d_out;           // [E] f32

    int n_h     = in_sizes[0];      // N*64 floats
    int n_edges = in_sizes[1];

    // K1: convert table to fp16 scratch (2 float4 per thread, 2 streams)
    int n4      = n_h / 4;
    int half_n4 = n4 / 2;
    int cblocks = (half_n4 + THREADS - 1) / THREADS;
    convert_kernel<<<cblocks, THREADS>>>(hf4, half_n4);

    // K2: gather + dot (4 edges per 8-lane group; E divisible by 4)
    int n_groups = n_edges / 4;
    long long total_threads = (long long)n_groups * 8;
    int blocks = (int)((total_threads + THREADS - 1) / THREADS);
    dot_predictor_kernel<<<blocks, THREADS>>>(src4, dst4, out, n_groups);
}